// round 17
// baseline (speedup 1.0000x reference)
#include <cuda_runtime.h>
#include <cuda_bf16.h>
#include <mma.h>
#include <cstdint>
#include <cstddef>

using namespace nvcuda;
typedef __nv_bfloat16 bf16;

#define BATCH 4
#define CQd   256
#define NQd   2048
#define NKVd  2048
#define NH    8
#define DKd   64
#define ODd   512   // NH*DKd
#define GSPLIT 4    // split-K for the Gram matrix

// ---------------- scratch (static device globals; no runtime alloc) -------
__device__ __align__(16) bf16  g_xq [BATCH*CQd*NQd];
__device__ __align__(16) bf16  g_xkv[BATCH*CQd*NKVd];
__device__ __align__(16) bf16  g_Wq [ODd*CQd];
__device__ __align__(16) bf16  g_Wk [ODd*CQd];
__device__ __align__(16) bf16  g_Wv [ODd*CQd];
__device__ __align__(16) bf16  g_Wo [CQd*ODd];
__device__ __align__(16) float g_Gpart[GSPLIT*BATCH*CQd*CQd];  // Gram partials
__device__ __align__(16) bf16  g_G  [BATCH*CQd*CQd];           // Gram bf16
__device__ __align__(16) bf16  g_Wp [BATCH*CQd*ODd];           // Wo @ blockdiag(M~^T)
__device__ __align__(16) bf16  g_E  [BATCH*CQd*CQd];           // Wp @ Wq

// ---------------- fused fp32 -> bf16 conversion (all 6 tensors) -----------
__global__ void convert_all_kernel(const float* __restrict__ xq,
                                   const float* __restrict__ xkv,
                                   const float* __restrict__ Wq,
                                   const float* __restrict__ Wk,
                                   const float* __restrict__ Wv,
                                   const float* __restrict__ Wo) {
    int i = blockIdx.x * blockDim.x + threadIdx.x;  // float4 index, total 1179648
    const float* src; bf16* dst; int off;
    if (i < 524288)            { src = xq;  dst = g_xq;  off = i; }
    else if (i < 1048576)      { src = xkv; dst = g_xkv; off = i - 524288; }
    else {
        int j = i - 1048576;
        int w = j >> 15;  off = j & 32767;
        src = (w == 0) ? Wq : (w == 1) ? Wk : (w == 2) ? Wv : Wo;
        dst = (w == 0) ? g_Wq : (w == 1) ? g_Wk : (w == 2) ? g_Wv : g_Wo;
    }
    float4 v = ((const float4*)src)[off];
    __nv_bfloat162 two[2] = { __floats2bfloat162_rn(v.x, v.y),
                              __floats2bfloat162_rn(v.z, v.w) };
    *(uint2*)&dst[(size_t)off * 4] = *(uint2*)two;
}

// ---------------- cp.async helpers -----------------------------------------
__device__ __forceinline__ void cpa16(void* dst, const void* src) {
    unsigned int d = (unsigned int)__cvta_generic_to_shared(dst);
    asm volatile("cp.async.cg.shared.global [%0], [%1], 16;\n" :: "r"(d), "l"(src));
}
__device__ __forceinline__ void cpa_commit() {
    asm volatile("cp.async.commit_group;\n" ::);
}

// ---------------- pipelined TOx128x32 bf16 GEMM core (proven config) -------
template<int CD, int TO>
__device__ __forceinline__ void stage_tiles(const bf16* __restrict__ W,
                                            const bf16* __restrict__ Xb,
                                            bf16* As, bf16* Bs,
                                            int o0, int n0, int k0, int tid) {
    #pragma unroll
    for (int ch = tid; ch < TO * 4; ch += 256) {   // A: TOx32
        int r = ch >> 2, cc = (ch & 3) * 8;
        cpa16(As + r * 40 + cc, W + (size_t)(o0 + r) * CD + k0 + cc);
    }
    #pragma unroll
    for (int ch = tid; ch < 512; ch += 256) {      // B: 32x128
        int r = ch >> 4, cc = (ch & 15) * 8;
        cpa16(Bs + r * 136 + cc, Xb + (size_t)(k0 + r) * NQd + n0 + cc);
    }
    cpa_commit();
}

template<bool FINAL, int CD, int TO>
__device__ __forceinline__ void gemm_core(const bf16* __restrict__ W,
                                          const bf16* __restrict__ Xb,
                                          bf16* __restrict__ Ybf,
                                          float* __restrict__ Yf,
                                          const float* __restrict__ resid,
                                          const float* __restrict__ gammap) {
    const int n0 = blockIdx.x * 128;
    const int o0 = blockIdx.y * TO;
    constexpr int ABUF = TO * 40;
    constexpr int BBUF = 32 * 136;
    constexpr int MI   = TO / 32;

    extern __shared__ __align__(16) char smem_raw[];
    bf16*  AsB = (bf16*)smem_raw;
    bf16*  BsB = (bf16*)(smem_raw + 2 * ABUF * 2);
    float* Cs  = (float*)smem_raw;

    const int tid  = threadIdx.x;
    const int warp = tid >> 5;
    const int wr   = warp >> 2;
    const int wc   = warp & 3;

    wmma::fragment<wmma::accumulator,16,16,16,float> acc[MI][2];
    #pragma unroll
    for (int i = 0; i < MI; i++)
        #pragma unroll
        for (int j = 0; j < 2; j++) wmma::fill_fragment(acc[i][j], 0.0f);

    constexpr int KT = CD / 32;
    stage_tiles<CD, TO>(W, Xb, AsB, BsB, o0, n0, 0, tid);

    for (int kt = 0; kt < KT; kt++) {
        if (kt + 1 < KT) {
            stage_tiles<CD, TO>(W, Xb, AsB + ((kt + 1) & 1) * ABUF,
                                        BsB + ((kt + 1) & 1) * BBUF,
                                o0, n0, (kt + 1) * 32, tid);
            asm volatile("cp.async.wait_group 1;\n" ::);
        } else {
            asm volatile("cp.async.wait_group 0;\n" ::);
        }
        __syncthreads();

        const bf16* As = AsB + (kt & 1) * ABUF;
        const bf16* Bs = BsB + (kt & 1) * BBUF;
        #pragma unroll
        for (int ks = 0; ks < 2; ks++) {
            wmma::fragment<wmma::matrix_a,16,16,16,bf16,wmma::row_major> af[MI];
            wmma::fragment<wmma::matrix_b,16,16,16,bf16,wmma::row_major> bg[2];
            #pragma unroll
            for (int i = 0; i < MI; i++)
                wmma::load_matrix_sync(af[i], As + (wr*(TO/2) + i*16) * 40 + ks*16, 40);
            #pragma unroll
            for (int j = 0; j < 2; j++)
                wmma::load_matrix_sync(bg[j], Bs + (ks*16) * 136 + wc*32 + j*16, 136);
            #pragma unroll
            for (int i = 0; i < MI; i++)
                #pragma unroll
                for (int j = 0; j < 2; j++)
                    wmma::mma_sync(acc[i][j], af[i], bg[j], acc[i][j]);
        }
        __syncthreads();
    }

    #pragma unroll
    for (int i = 0; i < MI; i++)
        #pragma unroll
        for (int j = 0; j < 2; j++)
            wmma::store_matrix_sync(&Cs[(wr*(TO/2) + i*16) * 132 + wc*32 + j*16],
                                    acc[i][j], 132, wmma::mem_row_major);
    __syncthreads();

    float g = 0.0f;
    if (FINAL) g = gammap[0];
    #pragma unroll
    for (int t = tid; t < TO * 32; t += 256) {
        int r = t >> 5, c4 = (t & 31) * 4;
        float4 v = *(float4*)&Cs[r * 132 + c4];
        size_t gi = (size_t)(o0 + r) * NQd + n0 + c4;
        if (FINAL) {
            float4 x = *(const float4*)&resid[gi];
            v.x = g * v.x + x.x;  v.y = g * v.y + x.y;
            v.z = g * v.z + x.z;  v.w = g * v.w + x.w;
            *(float4*)&Yf[gi] = v;
        } else {
            __nv_bfloat162 two[2] = { __floats2bfloat162_rn(v.x, v.y),
                                      __floats2bfloat162_rn(v.z, v.w) };
            *(uint2*)&Ybf[gi] = *(uint2*)two;
        }
    }
}

// ---------------- Gram partials: Gpart[ks,b] += X[i-rows] X[j-rows]^T ------
// grid (16 tiles, GSPLIT, BATCH) = 256 CTAs, 128 thr — kv_outer-proven shape.
__global__ void gram_kernel() {
    const int ti = blockIdx.x >> 2, tj = blockIdx.x & 3;
    const int ks = blockIdx.y, b = blockIdx.z;
    const bf16* Xb = g_xkv + (size_t)b * CQd * NKVd;
    const bf16* Xi = Xb + (size_t)(ti * 64) * NKVd;
    const bf16* Xj = Xb + (size_t)(tj * 64) * NKVd;
    const int warp = threadIdx.x >> 5, wr = warp >> 1, wc = warp & 1;

    wmma::fragment<wmma::accumulator,16,16,16,float> acc[2][2];
    #pragma unroll
    for (int i = 0; i < 2; i++)
        #pragma unroll
        for (int j = 0; j < 2; j++) wmma::fill_fragment(acc[i][j], 0.0f);

    const int k0 = ks * (NKVd / GSPLIT);
    for (int k = k0; k < k0 + NKVd / GSPLIT; k += 16) {
        wmma::fragment<wmma::matrix_a,16,16,16,bf16,wmma::row_major> af[2];
        wmma::fragment<wmma::matrix_b,16,16,16,bf16,wmma::col_major> bg[2];
        #pragma unroll
        for (int i = 0; i < 2; i++)
            wmma::load_matrix_sync(af[i], Xi + (size_t)(wr*32 + i*16) * NKVd + k, NKVd);
        #pragma unroll
        for (int j = 0; j < 2; j++)
            wmma::load_matrix_sync(bg[j], Xj + (size_t)(wc*32 + j*16) * NKVd + k, NKVd);
        #pragma unroll
        for (int i = 0; i < 2; i++)
            #pragma unroll
            for (int j = 0; j < 2; j++)
                wmma::mma_sync(acc[i][j], af[i], bg[j], acc[i][j]);
    }
    float* Gout = g_Gpart + ((size_t)ks * BATCH + b) * CQd * CQd;
    #pragma unroll
    for (int i = 0; i < 2; i++)
        #pragma unroll
        for (int j = 0; j < 2; j++)
            wmma::store_matrix_sync(Gout + (size_t)(ti*64 + wr*32 + i*16) * CQd
                                         + tj*64 + wc*32 + j*16,
                                    acc[i][j], CQd, wmma::mem_row_major);
}

// ---------------- reduce Gram partials (float4) -> bf16 --------------------
__global__ void reduce_g_kernel() {
    int i = blockIdx.x * blockDim.x + threadIdx.x;   // float4 index
    const int n4 = BATCH * CQd * CQd / 4;            // 65536
    if (i >= n4) return;
    const float4* src = (const float4*)g_Gpart;
    float4 s = src[i];
    #pragma unroll
    for (int ks = 1; ks < GSPLIT; ks++) {
        float4 v = src[(size_t)ks * n4 + i];
        s.x += v.x;  s.y += v.y;  s.z += v.z;  s.w += v.w;
    }
    __nv_bfloat162 two[2] = { __floats2bfloat162_rn(s.x, s.y),
                              __floats2bfloat162_rn(s.z, s.w) };
    *(uint2*)&g_G[(size_t)i * 4] = *(uint2*)two;
}

// ---------------- mchain: per (b,h): T=Wk_h G~; M~=T Wv_h^T/64; Wp=Wo_h M~^T
// grid (NH, BATCH) = 32 CTAs, 256 threads (8 warps).
// smem: Cs fp32 [17408] (69632B) | Tsh bf16 [64*264] (33792B) | Msh bf16 [64*72] (9216B)
__global__ void mchain_kernel() {
    const int h = blockIdx.x, b = blockIdx.y;
    extern __shared__ __align__(16) char smem_raw[];
    float* Cs  = (float*)smem_raw;                     // >= 256*68 floats
    bf16*  Tsh = (bf16*)(smem_raw + 69632);            // [64][264]
    bf16*  Msh = (bf16*)(smem_raw + 69632 + 33792);    // [64][72]

    const int tid = threadIdx.x;
    const int w   = tid >> 5;
    const bf16* Gb = g_G + (size_t)b * CQd * CQd;

    // ---- phase T: T(64x256) = Wk_h(64x256) @ G~_b(256x256) ----
    {
        const int wr = w >> 1, wc = w & 1;   // rows wr*16, cols wc*128
        wmma::fragment<wmma::accumulator,16,16,16,float> acc[8];
        #pragma unroll
        for (int j = 0; j < 8; j++) wmma::fill_fragment(acc[j], 0.0f);
        #pragma unroll
        for (int kt = 0; kt < 16; kt++) {
            wmma::fragment<wmma::matrix_a,16,16,16,bf16,wmma::row_major> af;
            wmma::load_matrix_sync(af,
                g_Wk + (size_t)(h*64 + wr*16) * CQd + kt*16, CQd);
            #pragma unroll
            for (int j = 0; j < 8; j++) {
                wmma::fragment<wmma::matrix_b,16,16,16,bf16,wmma::row_major> bg;
                wmma::load_matrix_sync(bg,
                    Gb + (size_t)(kt*16) * CQd + wc*128 + j*16, CQd);
                wmma::mma_sync(acc[j], af, bg, acc[j]);
            }
        }
        #pragma unroll
        for (int j = 0; j < 8; j++)
            wmma::store_matrix_sync(&Cs[(wr*16) * 260 + wc*128 + j*16],
                                    acc[j], 260, wmma::mem_row_major);
    }
    __syncthreads();
    // convert T to bf16 in Tsh (ldm 264)
    #pragma unroll
    for (int t = tid; t < 4096; t += 256) {   // 64*256/4
        int r = t >> 6, c4 = (t & 63) * 4;
        float4 v = *(float4*)&Cs[r * 260 + c4];
        __nv_bfloat162 two[2] = { __floats2bfloat162_rn(v.x, v.y),
                                  __floats2bfloat162_rn(v.z, v.w) };
        *(uint2*)&Tsh[r * 264 + c4] = *(uint2*)two;
    }
    __syncthreads();

    // ---- phase M: M(64x64) = T(64x256) @ Wv_h^T(256x64), scaled 1/64 ----
    {
        const int wr = w >> 1, wc = w & 1;   // rows wr*16, cols wc*32
        wmma::fragment<wmma::accumulator,16,16,16,float> acc[2];
        #pragma unroll
        for (int j = 0; j < 2; j++) wmma::fill_fragment(acc[j], 0.0f);
        #pragma unroll
        for (int kt = 0; kt < 16; kt++) {
            wmma::fragment<wmma::matrix_a,16,16,16,bf16,wmma::row_major> af;
            wmma::load_matrix_sync(af, Tsh + (wr*16) * 264 + kt*16, 264);
            #pragma unroll
            for (int j = 0; j < 2; j++) {
                wmma::fragment<wmma::matrix_b,16,16,16,bf16,wmma::col_major> bg;
                wmma::load_matrix_sync(bg,
                    g_Wv + (size_t)(h*64 + wc*32 + j*16) * CQd + kt*16, CQd);
                wmma::mma_sync(acc[j], af, bg, acc[j]);
            }
        }
        #pragma unroll
        for (int j = 0; j < 2; j++)
            wmma::store_matrix_sync(&Cs[(wr*16) * 68 + wc*32 + j*16],
                                    acc[j], 68, wmma::mem_row_major);
    }
    __syncthreads();
    // convert+scale M to bf16 Msh (ldm 72)
    {
        const float sc = 1.0f / DKd;
        #pragma unroll
        for (int t = tid; t < 1024; t += 256) {   // 64*64/4
            int r = t >> 4, c4 = (t & 15) * 4;
            float4 v = *(float4*)&Cs[r * 68 + c4];
            __nv_bfloat162 two[2] = { __floats2bfloat162_rn(v.x * sc, v.y * sc),
                                      __floats2bfloat162_rn(v.z * sc, v.w * sc) };
            *(uint2*)&Msh[r * 72 + c4] = *(uint2*)two;
        }
    }
    __syncthreads();

    // ---- phase Wp: Wp_h(256x64) = Wo_h(256x64) @ M~^T(64x64) ----
    {
        wmma::fragment<wmma::accumulator,16,16,16,float> acc[2][4];
        #pragma unroll
        for (int i = 0; i < 2; i++)
            #pragma unroll
            for (int j = 0; j < 4; j++) wmma::fill_fragment(acc[i][j], 0.0f);
        #pragma unroll
        for (int kt = 0; kt < 4; kt++) {
            wmma::fragment<wmma::matrix_a,16,16,16,bf16,wmma::row_major> af[2];
            wmma::fragment<wmma::matrix_b,16,16,16,bf16,wmma::col_major> bg[4];
            #pragma unroll
            for (int i = 0; i < 2; i++)
                wmma::load_matrix_sync(af[i],
                    g_Wo + (size_t)(w*32 + i*16) * ODd + h*64 + kt*16, ODd);
            #pragma unroll
            for (int j = 0; j < 4; j++)   // B(e,d) = M~[d,e] -> col_major ldm 72
                wmma::load_matrix_sync(bg[j], Msh + (j*16) * 72 + kt*16, 72);
            #pragma unroll
            for (int i = 0; i < 2; i++)
                #pragma unroll
                for (int j = 0; j < 4; j++)
                    wmma::mma_sync(acc[i][j], af[i], bg[j], acc[i][j]);
        }
        #pragma unroll
        for (int i = 0; i < 2; i++)
            #pragma unroll
            for (int j = 0; j < 4; j++)
                wmma::store_matrix_sync(&Cs[(w*32 + i*16) * 68 + j*16],
                                        acc[i][j], 68, wmma::mem_row_major);
    }
    __syncthreads();

    // write Wp slice (256 x 64 bf16) into g_Wp[b][:, h*64..]
    bf16* Wpb = g_Wp + (size_t)b * CQd * ODd;
    #pragma unroll
    for (int t = tid; t < 4096; t += 256) {   // 256*64/4
        int r = t >> 4, c4 = (t & 15) * 4;
        float4 v = *(float4*)&Cs[r * 68 + c4];
        __nv_bfloat162 two[2] = { __floats2bfloat162_rn(v.x, v.y),
                                  __floats2bfloat162_rn(v.z, v.w) };
        *(uint2*)&Wpb[(size_t)r * ODd + h*64 + c4] = *(uint2*)two;
    }
}

// ---------------- ewq: E_b(256x256) = Wp_b(256x512) @ Wq(512x256) ----------
// grid (4, 4, BATCH) = 64 CTAs, 128 threads, direct-global wmma (womt-style).
__global__ void ewq_kernel() {
    const int j0 = blockIdx.x * 64, i0 = blockIdx.y * 64, b = blockIdx.z;
    const bf16* Wpb = g_Wp + (size_t)b * CQd * ODd;
    __shared__ __align__(16) float Cs[64][68];
    const int tid = threadIdx.x;
    const int warp = tid >> 5, wr = warp >> 1, wc = warp & 1;

    wmma::fragment<wmma::accumulator,16,16,16,float> acc[2][2];
    #pragma unroll
    for (int i = 0; i < 2; i++)
        #pragma unroll
        for (int j = 0; j < 2; j++) wmma::fill_fragment(acc[i][j], 0.0f);

    for (int k = 0; k < ODd; k += 16) {
        wmma::fragment<wmma::matrix_a,16,16,16,bf16,wmma::row_major> af[2];
        wmma::fragment<wmma::matrix_b,16,16,16,bf16,wmma::row_major> bg[2];
        #pragma unroll
        for (int i = 0; i < 2; i++)
            wmma::load_matrix_sync(af[i],
                Wpb + (size_t)(i0 + wr*32 + i*16) * ODd + k, ODd);
        #pragma unroll
        for (int j = 0; j < 2; j++)
            wmma::load_matrix_sync(bg[j],
                g_Wq + (size_t)k * CQd + j0 + wc*32 + j*16, CQd);
        #pragma unroll
        for (int i = 0; i < 2; i++)
            #pragma unroll
            for (int j = 0; j < 2; j++)
                wmma::mma_sync(acc[i][j], af[i], bg[j], acc[i][j]);
    }
    #pragma unroll
    for (int i = 0; i < 2; i++)
        #pragma unroll
        for (int j = 0; j < 2; j++)
            wmma::store_matrix_sync(&Cs[wr*32 + i*16][wc*32 + j*16], acc[i][j], 68,
                                    wmma::mem_row_major);
    __syncthreads();

    bf16* Eb = g_E + (size_t)b * CQd * CQd;
    #pragma unroll
    for (int t = tid; t < 1024; t += 128) {
        int r = t >> 4, c4 = (t & 15) * 4;
        float4 v = *(float4*)&Cs[r][c4];
        __nv_bfloat162 two[2] = { __floats2bfloat162_rn(v.x, v.y),
                                  __floats2bfloat162_rn(v.z, v.w) };
        *(uint2*)&Eb[(size_t)(i0 + r) * CQd + j0 + c4] = *(uint2*)two;
    }
}

// ---------------- final: out = gamma * (E_b @ x_q_b) + x_q ------------------
__global__ void final_kernel(const float* __restrict__ xq,
                             const float* __restrict__ gammap,
                             float* __restrict__ out) {
    int b = blockIdx.z;
    gemm_core<true, CQd, 64>(g_E  + (size_t)b * CQd * CQd,
                             g_xq + (size_t)b * CQd * NQd,
                             nullptr,
                             out + (size_t)b * CQd * NQd,
                             xq  + (size_t)b * CQd * NQd,
                             gammap);
}

// ---------------------------------------------------------------------------
extern "C" void kernel_launch(void* const* d_in, const int* in_sizes, int n_in,
                              void* d_out, int out_size) {
    const float* xq    = (const float*)d_in[0];
    const float* xkv   = (const float*)d_in[1];
    const float* Wq    = (const float*)d_in[2];
    const float* Wk    = (const float*)d_in[3];
    const float* Wv    = (const float*)d_in[4];
    const float* Wo    = (const float*)d_in[5];
    const float* gamma = (const float*)d_in[6];
    float* out = (float*)d_out;

    cudaFuncSetAttribute(mchain_kernel, cudaFuncAttributeMaxDynamicSharedMemorySize, 112640);
    cudaFuncSetAttribute(final_kernel,  cudaFuncAttributeMaxDynamicSharedMemorySize, 34816);

    // 1) convert everything to bf16
    convert_all_kernel<<<4608, 256>>>(xq, xkv, Wq, Wk, Wv, Wo);

    // 2) Gram: G_b = x_kv x_kv^T (split-K partials, 256 CTAs)
    gram_kernel<<<dim3(16, GSPLIT, BATCH), 128>>>();
    reduce_g_kernel<<<256, 256>>>();

    // 3) per-(b,h) chain: T = Wk_h G~;  M~ = T Wv_h^T / 64;  Wp_h = Wo_h M~^T
    mchain_kernel<<<dim3(NH, BATCH), 256, 112640>>>();

    // 4) E_b = Wp_b @ Wq  (collapses Q projection + final into one operator)
    ewq_kernel<<<dim3(4, 4, BATCH), 128>>>();

    // 5) out = gamma * (E_b @ x_q) + x_q
    final_kernel<<<dim3(NQd/128, CQd/64, BATCH), 256, 33792>>>(xq, gamma, out);
}